// round 16
// baseline (speedup 1.0000x reference)
#include <cuda_runtime.h>
#include <cuda_bf16.h>
#include <math.h>

// Problem constants
#define TT 512
#define BB 64
#define EE 256
#define HH 256      // per-direction hidden
#define GG 1024     // 4*HH
#define KK 13
#define MM (TT*BB)  // 32768

// ---------------- scratch (static device globals; no allocation in launch) ----
__device__ float g_xg[2][(size_t)MM * GG];         // gate preacts [dir][m][gate]
__device__ float g_h[2][(size_t)TT * HH * BB];     // hidden [dir][t][u][b]
__device__ float g_emis[(size_t)MM * KK];          // emissions [t][b][k]
__device__ int   g_arrive[2][64];                  // per-CTA progress: steps completed

// scalar Kahan merge (intrinsics -> no reassociation)
#define KMERGE(acc, comp, p) do {                      \
    float _y = __fsub_rn((p), (comp));                 \
    float _t = __fadd_rn((acc), _y);                   \
    (comp) = __fsub_rn(__fsub_rn(_t, (acc)), _y);      \
    (acc) = _t;                                        \
} while (0)

// ---------------- double-single helpers (FFMA pipe only) -------
__device__ __forceinline__ float2 two_sum(float a, float b) {
    float s  = __fadd_rn(a, b);
    float bp = __fsub_rn(s, a);
    float e  = __fadd_rn(__fsub_rn(a, __fsub_rn(s, bp)), __fsub_rn(b, bp));
    return make_float2(s, e);
}
__device__ __forceinline__ float2 quick_two_sum(float a, float b) {  // |a| >= |b|
    float s = __fadd_rn(a, b);
    float e = __fsub_rn(b, __fsub_rn(s, a));
    return make_float2(s, e);
}
__device__ __forceinline__ float2 two_prod(float a, float b) {
    float p = __fmul_rn(a, b);
    float e = __fmaf_rn(a, b, -p);
    return make_float2(p, e);
}
__device__ __forceinline__ float2 exp_ds(float x) {
    x = fmaxf(-30.0f, fminf(30.0f, x));
    float n  = rintf(__fmul_rn(x, 1.4426950408889634f));
    float r1 = __fmaf_rn(n, -0.693359375f, x);
    float2 p = two_prod(n, 2.1219444e-4f);
    float2 r = two_sum(r1, p.x);
    float rh = r.x;
    float rl = __fadd_rn(r.y, p.y);
    float t = 1.9841270e-4f;
    t = __fmaf_rn(t, rh, 1.3888889e-3f);
    t = __fmaf_rn(t, rh, 8.3333333e-3f);
    t = __fmaf_rn(t, rh, 4.1666667e-2f);
    t = __fmaf_rn(t, rh, 1.6666667e-1f);
    float rr   = __fmul_rn(rh, rh);
    float tail = __fmul_rn(__fmul_rn(rr, rh), t);
    tail = __fmaf_rn(rl, __fadd_rn(1.0f, rh), tail);
    float2 h2 = two_prod(rh, rh);
    float hx = __fmul_rn(0.5f, h2.x), hy = __fmul_rn(0.5f, h2.y);
    float2 a  = quick_two_sum(rh, hx);
    float al  = __fadd_rn(a.y, hy);
    float2 b  = two_sum(a.x, tail);
    float bl  = __fadd_rn(b.y, al);
    float2 c  = quick_two_sum(1.0f, b.x);
    float cl  = __fadd_rn(c.y, bl);
    float sc  = __int_as_float(((int)n + 127) << 23);
    return make_float2(__fmul_rn(c.x, sc), __fmul_rn(cl, sc));
}
__device__ __forceinline__ float2 sigmoid_ds(float x) {
    float2 E = exp_ds(-x);
    float2 D = two_sum(1.0f, E.x);
    float Dl = __fadd_rn(D.y, E.y);
    float y  = __frcp_rn(D.x);
    float e  = __fmaf_rn(-D.x, y, 1.0f);
    e        = __fmaf_rn(-Dl, y, e);
    return make_float2(y, __fmul_rn(y, e));
}
__device__ __forceinline__ float2 tanh_ds(float x) {
    float2 E = exp_ds(__fmul_rn(2.0f, x));
    float2 num = two_sum(E.x, -1.0f);
    float numl = __fadd_rn(num.y, E.y);
    float2 den = two_sum(E.x, 1.0f);
    float denl = __fadd_rn(den.y, E.y);
    float q  = __fdiv_rn(num.x, den.x);
    float rr = __fmaf_rn(-q, den.x, num.x);
    rr = __fadd_rn(rr, __fmaf_rn(-q, denl, numl));
    float ql = __fmul_rn(rr, __frcp_rn(den.x));
    return make_float2(q, ql);
}

// ---------------- 0: zero arrival slots ----------------
__global__ void zero_cnt_kernel() {
    int i = threadIdx.x;
    if (i < 128) ((int*)g_arrive)[i] = 0;
}

// ---------------- 1: input GEMM with fused gather (R14-exact) ----------------
__global__ __launch_bounds__(256) void xg_gemm_kernel(
    const int* __restrict__ x, const float* __restrict__ emb,
    const float* __restrict__ wf, const float* __restrict__ wb,
    const float* __restrict__ bihf, const float* __restrict__ bhhf,
    const float* __restrict__ bihb, const float* __restrict__ bhhb)
{
    __shared__ float ash[16][64];   // [k][m]
    __shared__ float bsh[16][64];   // [k][n]

    int dir = blockIdx.z;
    const float* W  = dir ? wb : wf;
    const float* B1 = dir ? bihb : bihf;
    const float* B2 = dir ? bhhb : bhhf;
    float* Cout = g_xg[dir];

    int t  = blockIdx.x;
    int m0 = t * 64;
    int n0 = blockIdx.y * 64;
    int tid = threadIdx.x;
    int tx = tid & 15;
    int ty = tid >> 4;

    float acc[4][4], cmp[4][4];
#pragma unroll
    for (int i = 0; i < 4; i++)
#pragma unroll
        for (int j = 0; j < 4; j++) { acc[i][j] = 0.f; cmp[i][j] = 0.f; }

    int ml = tid >> 2;        // 0..63 (row in tile == batch b)
    int kq = tid & 3;

    int tok = x[ml * TT + t];
    const float* arow = emb + (size_t)tok * EE;
    const float* brow = W + (size_t)(n0 + ml) * EE;

    for (int k0 = 0; k0 < EE; k0 += 16) {
        float4 av = *(const float4*)(arow + k0 + kq * 4);
        float4 bv = *(const float4*)(brow + k0 + kq * 4);
        ash[kq * 4 + 0][ml] = av.x; ash[kq * 4 + 1][ml] = av.y;
        ash[kq * 4 + 2][ml] = av.z; ash[kq * 4 + 3][ml] = av.w;
        bsh[kq * 4 + 0][ml] = bv.x; bsh[kq * 4 + 1][ml] = bv.y;
        bsh[kq * 4 + 2][ml] = bv.z; bsh[kq * 4 + 3][ml] = bv.w;
        __syncthreads();

        float part[4][4];
#pragma unroll
        for (int i = 0; i < 4; i++)
#pragma unroll
            for (int j = 0; j < 4; j++) part[i][j] = 0.f;

#pragma unroll
        for (int kk = 0; kk < 16; kk++) {
            float4 a4 = *(const float4*)&ash[kk][ty * 4];
            float4 b4 = *(const float4*)&bsh[kk][tx * 4];
            part[0][0] = __fmaf_rn(a4.x, b4.x, part[0][0]); part[0][1] = __fmaf_rn(a4.x, b4.y, part[0][1]);
            part[0][2] = __fmaf_rn(a4.x, b4.z, part[0][2]); part[0][3] = __fmaf_rn(a4.x, b4.w, part[0][3]);
            part[1][0] = __fmaf_rn(a4.y, b4.x, part[1][0]); part[1][1] = __fmaf_rn(a4.y, b4.y, part[1][1]);
            part[1][2] = __fmaf_rn(a4.y, b4.z, part[1][2]); part[1][3] = __fmaf_rn(a4.y, b4.w, part[1][3]);
            part[2][0] = __fmaf_rn(a4.z, b4.x, part[2][0]); part[2][1] = __fmaf_rn(a4.z, b4.y, part[2][1]);
            part[2][2] = __fmaf_rn(a4.z, b4.z, part[2][2]); part[2][3] = __fmaf_rn(a4.z, b4.w, part[2][3]);
            part[3][0] = __fmaf_rn(a4.w, b4.x, part[3][0]); part[3][1] = __fmaf_rn(a4.w, b4.y, part[3][1]);
            part[3][2] = __fmaf_rn(a4.w, b4.z, part[3][2]); part[3][3] = __fmaf_rn(a4.w, b4.w, part[3][3]);
        }
#pragma unroll
        for (int i = 0; i < 4; i++)
#pragma unroll
            for (int j = 0; j < 4; j++) KMERGE(acc[i][j], cmp[i][j], part[i][j]);
        __syncthreads();
    }

    float bias[4];
#pragma unroll
    for (int j = 0; j < 4; j++) {
        int n = n0 + tx * 4 + j;
        bias[j] = B1[n] + B2[n];
    }
#pragma unroll
    for (int i = 0; i < 4; i++) {
        float4 r;
        r.x = __fsub_rn(acc[i][0], cmp[i][0]) + bias[0];
        r.y = __fsub_rn(acc[i][1], cmp[i][1]) + bias[1];
        r.z = __fsub_rn(acc[i][2], cmp[i][2]) + bias[2];
        r.w = __fsub_rn(acc[i][3], cmp[i][3]) + bias[3];
        *(float4*)(Cout + (size_t)(m0 + ty * 4 + i) * GG + n0 + tx * 4) = r;
    }
}

// ---------------- 2: persistent BiLSTM (slot sync; gate buffer; 1-thread fence)
#define LSTM_SMEM_FLOATS (4096 + 16384 + 1024 + 256 + 1024)
__global__ __launch_bounds__(256) void lstm_persist_kernel(const float* __restrict__ wf,
                                                           const float* __restrict__ wb)
{
    extern __shared__ float sm[];
    float* wsh = sm;                    // [16][256]
    float* hsh = sm + 4096;             // [256][64]
    float* xsh = sm + 4096 + 16384;     // [16][64]  xg staging
    float* csh = xsh + 1024;            // [4][64]   cell state
    float* gsh = csh + 256;             // [16][64]  gate results (separate buffer)

    int tid = threadIdx.x;
    int dir = blockIdx.x >> 6;
    int g   = blockIdx.x & 63;
    const float* W = dir ? wb : wf;
    const float* xg = g_xg[dir];
    float* hbase = g_h[dir];
    volatile int* arr = (volatile int*)g_arrive[dir];

    for (int i = tid; i < 1024; i += 256) {
        int rr = i >> 6;
        int e4 = i & 63;
        int grow = (rr >> 2) * 256 + g * 4 + (rr & 3);
        *(float4*)(wsh + rr * 256 + e4 * 4) =
            *(const float4*)(W + (size_t)grow * 256 + e4 * 4);
    }
    csh[tid] = 0.f;
    __syncthreads();

    int r2 = tid >> 5;
    int b2 = tid & 31;
    int du = tid >> 6;
    int bb = tid & 63;

    for (int s = 0; s < TT; s++) {
        int t = dir ? (TT - 1 - s) : s;

        // stage this CTA's xg slice: 64 b x 4 q float4s
        {
            int b = tid >> 2, q = tid & 3;
            float4 v = *(const float4*)(xg + (size_t)(t * 64 + b) * GG + q * 256 + g * 4);
            xsh[(q * 4 + 0) * 64 + b] = v.x;
            xsh[(q * 4 + 1) * 64 + b] = v.y;
            xsh[(q * 4 + 2) * 64 + b] = v.z;
            xsh[(q * 4 + 3) * 64 + b] = v.w;
        }

        if (s > 0) {
            // distributed wait: thread i watches CTA i's progress slot
            if (tid < 64) {
                while (arr[tid] < s) { }
            }
            __syncthreads();
            int tp = dir ? (t + 1) : (t - 1);
            const float* hp = hbase + (size_t)tp * (HH * BB);
            for (int i = tid; i < 4096; i += 256)
                *(float4*)(hsh + i * 4) = *(const float4*)(hp + i * 4);
        }
        __syncthreads();

        // Kahan fp32 dot over 256 h-terms: 16 chunks of 16 (R9-exact order)
        float a00 = 0.f, a01 = 0.f, a10 = 0.f, a11 = 0.f;
        float k00 = 0.f, k01 = 0.f, k10 = 0.f, k11 = 0.f;
        if (s > 0) {
            const float* w0p = wsh + r2 * 256;
            const float* w1p = wsh + (r2 + 8) * 256;
#pragma unroll
            for (int e16 = 0; e16 < 16; e16++) {
                float p00 = 0.f, p01 = 0.f, p10 = 0.f, p11 = 0.f;
#pragma unroll
                for (int q = 0; q < 4; q++) {
                    int e4 = e16 * 4 + q;
                    float4 w0 = *(const float4*)(w0p + e4 * 4);
                    float4 w1 = *(const float4*)(w1p + e4 * 4);
                    const float* hp0 = hsh + e4 * 256 + b2;
                    float h0, h1;
                    h0 = hp0[0];   h1 = hp0[32];
                    p00 = __fmaf_rn(w0.x, h0, p00); p01 = __fmaf_rn(w0.x, h1, p01);
                    p10 = __fmaf_rn(w1.x, h0, p10); p11 = __fmaf_rn(w1.x, h1, p11);
                    h0 = hp0[64];  h1 = hp0[96];
                    p00 = __fmaf_rn(w0.y, h0, p00); p01 = __fmaf_rn(w0.y, h1, p01);
                    p10 = __fmaf_rn(w1.y, h0, p10); p11 = __fmaf_rn(w1.y, h1, p11);
                    h0 = hp0[128]; h1 = hp0[160];
                    p00 = __fmaf_rn(w0.z, h0, p00); p01 = __fmaf_rn(w0.z, h1, p01);
                    p10 = __fmaf_rn(w1.z, h0, p10); p11 = __fmaf_rn(w1.z, h1, p11);
                    h0 = hp0[192]; h1 = hp0[224];
                    p00 = __fmaf_rn(w0.w, h0, p00); p01 = __fmaf_rn(w0.w, h1, p01);
                    p10 = __fmaf_rn(w1.w, h0, p10); p11 = __fmaf_rn(w1.w, h1, p11);
                }
                KMERGE(a00, k00, p00); KMERGE(a01, k01, p01);
                KMERGE(a10, k10, p10); KMERGE(a11, k11, p11);
            }
        }
        // gates -> separate buffer (no conflict with xsh readers; 1 barrier)
        gsh[r2 * 64 + b2]             = xsh[r2 * 64 + b2]            + __fsub_rn(a00, k00);
        gsh[r2 * 64 + b2 + 32]        = xsh[r2 * 64 + b2 + 32]       + __fsub_rn(a01, k01);
        gsh[(r2 + 8) * 64 + b2]       = xsh[(r2 + 8) * 64 + b2]      + __fsub_rn(a10, k10);
        gsh[(r2 + 8) * 64 + b2 + 32]  = xsh[(r2 + 8) * 64 + b2 + 32] + __fsub_rn(a11, k11);
        __syncthreads();

        // activation (double-single; quantize at c and h) — R9-exact
        {
            float iv = gsh[(0 + du) * 64 + bb];
            float fv = gsh[(4 + du) * 64 + bb];
            float gv = gsh[(8 + du) * 64 + bb];
            float ov = gsh[(12 + du) * 64 + bb];
            float c  = csh[du * 64 + bb];

            float2 sf = sigmoid_ds(fv);
            float2 si = sigmoid_ds(iv);
            float2 tg = tanh_ds(gv);
            float2 p1 = two_prod(sf.x, c);
            float p1l = __fmaf_rn(sf.y, c, p1.y);
            float2 p2 = two_prod(si.x, tg.x);
            float p2l = __fmaf_rn(si.x, tg.y, __fmaf_rn(si.y, tg.x, p2.y));
            float2 sck = two_sum(p1.x, p2.x);
            float cf = __fadd_rn(sck.x, __fadd_rn(sck.y, __fadd_rn(p1l, p2l)));

            float2 so = sigmoid_ds(ov);
            float2 tc = tanh_ds(cf);
            float2 ph = two_prod(so.x, tc.x);
            float phl = __fmaf_rn(so.x, tc.y, __fmaf_rn(so.y, tc.x, ph.y));
            float hf = __fadd_rn(ph.x, phl);

            csh[du * 64 + bb] = cf;
            hbase[(size_t)t * (HH * BB) + (g * 4 + du) * 64 + bb] = hf;
        }
        __syncthreads();
        if (tid == 0) {
            __threadfence();            // cumulative: orders all threads' h STGs
            arr[g] = s + 1;             // own slot: plain store, no RMW
        }
    }
}

// ---------------- 3: emissions = kahan_dot([h_f|h_b], w_out) + b_out ----------
__global__ __launch_bounds__(256) void emis_kernel(const float* __restrict__ wout,
                                                   const float* __restrict__ bout)
{
    __shared__ float wsh[KK * 512];
    int t = blockIdx.x;
    int tid = threadIdx.x;

    for (int i = tid; i < (KK * 512) / 4; i += 256)
        *(float4*)(wsh + i * 4) = *(const float4*)(wout + i * 4);
    __syncthreads();

    int b = tid & 63;
    int kslot = tid >> 6;

    float acc[4] = {0.f, 0.f, 0.f, 0.f};
    float cmp[4] = {0.f, 0.f, 0.f, 0.f};

    const float* hf = g_h[0] + (size_t)t * (HH * BB);
    const float* hb = g_h[1] + (size_t)t * (HH * BB);

    for (int half = 0; half < 2; half++) {
        const float* hsrc = half ? hb : hf;
        int woff = half ? 256 : 0;
        for (int u0 = 0; u0 < HH; u0 += 16) {
            float part[4] = {0.f, 0.f, 0.f, 0.f};
#pragma unroll
            for (int uu = 0; uu < 16; uu++) {
                float v = hsrc[(u0 + uu) * 64 + b];
#pragma unroll
                for (int i = 0; i < 4; i++) {
                    int k = kslot + 4 * i;
                    if (k < KK)
                        part[i] = __fmaf_rn(v, wsh[k * 512 + woff + u0 + uu], part[i]);
                }
            }
#pragma unroll
            for (int i = 0; i < 4; i++) KMERGE(acc[i], cmp[i], part[i]);
        }
    }
#pragma unroll
    for (int i = 0; i < 4; i++) {
        int k = kslot + 4 * i;
        if (k < KK)
            g_emis[((size_t)t * 64 + b) * KK + k] = __fsub_rn(acc[i], cmp[i]) + bout[k];
    }
}

// ---------------- 4: CRF Viterbi, warp-per-batch, smem-resident ----------
#define VIT_EM_FLOATS (TT * 16)
#define VIT_SMEM_BYTES ((VIT_EM_FLOATS + 176 + 16) * 4 + (TT - 1) * 16)
__global__ __launch_bounds__(32) void viterbi_kernel(const float* __restrict__ start_t,
                                                     const float* __restrict__ end_t,
                                                     const float* __restrict__ trans,
                                                     float* __restrict__ out, int out_size)
{
    extern __shared__ float vsm[];
    float* em_s = vsm;                                   // [512][16]
    float* tr   = vsm + VIT_EM_FLOATS;                   // [169] (+pad)
    float* ssc  = tr + 176;                              // [16]
    unsigned char* bps = (unsigned char*)(ssc + 16);     // [511][16]

    int k = threadIdx.x;
    int b = blockIdx.x;
    bool act = (k < KK);

    for (int i = k; i < VIT_EM_FLOATS; i += 32) {
        int t = i >> 4, kk = i & 15;
        em_s[i] = (kk < KK) ? g_emis[((size_t)t * 64 + b) * KK + kk] : 0.f;
    }
    for (int i = k; i < 169; i += 32) tr[i] = trans[i];
    __syncwarp();

    float trcol[KK];
#pragma unroll
    for (int j = 0; j < KK; j++) trcol[j] = act ? tr[j * KK + k] : 0.f;

    float sc = act ? (start_t[k] + em_s[k]) : -1e30f;

    for (int t = 1; t < TT; t++) {
        if (act) ssc[k] = sc;
        __syncwarp();
        float best = -1e30f;
        int arg = 0;
        if (act) {
            float em = em_s[t * 16 + k];
            best = (ssc[0] + trcol[0]) + em;
#pragma unroll
            for (int j = 1; j < KK; j++) {
                float v = (ssc[j] + trcol[j]) + em;
                if (v > best) { best = v; arg = j; }
            }
            bps[(t - 1) * 16 + k] = (unsigned char)arg;
        }
        __syncwarp();
        sc = best;
    }

    if (act) ssc[k] = sc + end_t[k];
    __syncwarp();

    if (k == 0) {
        float best = ssc[0];
        int arg = 0;
#pragma unroll
        for (int j = 1; j < KK; j++) {
            float v = ssc[j];
            if (v > best) { best = v; arg = j; }
        }
        if (out_size >= MM + BB) out[MM + b] = best;
        int tag = arg;
        out[(size_t)b * TT + (TT - 1)] = (float)tag;
        for (int t = TT - 2; t >= 0; t--) {
            tag = bps[t * 16 + tag];
            out[(size_t)b * TT + t] = (float)tag;
        }
    }
}

// ---------------- launch ----------------
extern "C" void kernel_launch(void* const* d_in, const int* in_sizes, int n_in,
                              void* d_out, int out_size)
{
    const int*   x       = (const int*)  d_in[0];
    const float* emb     = (const float*)d_in[1];
    const float* w_ih_f  = (const float*)d_in[2];
    const float* w_hh_f  = (const float*)d_in[3];
    const float* b_ih_f  = (const float*)d_in[4];
    const float* b_hh_f  = (const float*)d_in[5];
    const float* w_ih_b  = (const float*)d_in[6];
    const float* w_hh_b  = (const float*)d_in[7];
    const float* b_ih_b  = (const float*)d_in[8];
    const float* b_hh_b  = (const float*)d_in[9];
    const float* w_out   = (const float*)d_in[10];
    const float* b_out   = (const float*)d_in[11];
    const float* start_t = (const float*)d_in[12];
    const float* end_t   = (const float*)d_in[13];
    const float* trans   = (const float*)d_in[14];
    float* out = (float*)d_out;

    cudaFuncSetAttribute(lstm_persist_kernel,
                         cudaFuncAttributeMaxDynamicSharedMemorySize,
                         LSTM_SMEM_FLOATS * 4);
    cudaFuncSetAttribute(viterbi_kernel,
                         cudaFuncAttributeMaxDynamicSharedMemorySize,
                         VIT_SMEM_BYTES);

    zero_cnt_kernel<<<1, 128>>>();
    dim3 gg(512, 16, 2);
    xg_gemm_kernel<<<gg, 256>>>(x, emb, w_ih_f, w_ih_b,
                                b_ih_f, b_hh_f, b_ih_b, b_hh_b);
    lstm_persist_kernel<<<128, 256, LSTM_SMEM_FLOATS * 4>>>(w_hh_f, w_hh_b);
    emis_kernel<<<TT, 256>>>(w_out, b_out);
    viterbi_kernel<<<64, 32, VIT_SMEM_BYTES>>>(start_t, end_t, trans, out, out_size);
}

// round 17
// speedup vs baseline: 1.0560x; 1.0560x over previous
#include <cuda_runtime.h>
#include <cuda_bf16.h>
#include <math.h>

// Problem constants
#define TT 512
#define BB 64
#define EE 256
#define HH 256      // per-direction hidden
#define GG 1024     // 4*HH
#define KK 13
#define MM (TT*BB)  // 32768

// ---------------- scratch (static device globals; no allocation in launch) ----
__device__ float g_xg[2][(size_t)MM * GG];         // gate preacts [dir][m][gate]
__device__ float g_h[2][(size_t)TT * HH * BB];     // hidden [dir][t][u][b]
__device__ float g_emis[(size_t)MM * KK];          // emissions [t][b][k]
__device__ int   g_arrive[2][64];                  // per-CTA progress: steps completed

// scalar Kahan merge (intrinsics -> no reassociation)
#define KMERGE(acc, comp, p) do {                      \
    float _y = __fsub_rn((p), (comp));                 \
    float _t = __fadd_rn((acc), _y);                   \
    (comp) = __fsub_rn(__fsub_rn(_t, (acc)), _y);      \
    (acc) = _t;                                        \
} while (0)

// ---------------- double-single helpers (FFMA pipe only) -------
__device__ __forceinline__ float2 two_sum(float a, float b) {
    float s  = __fadd_rn(a, b);
    float bp = __fsub_rn(s, a);
    float e  = __fadd_rn(__fsub_rn(a, __fsub_rn(s, bp)), __fsub_rn(b, bp));
    return make_float2(s, e);
}
__device__ __forceinline__ float2 quick_two_sum(float a, float b) {  // |a| >= |b|
    float s = __fadd_rn(a, b);
    float e = __fsub_rn(b, __fsub_rn(s, a));
    return make_float2(s, e);
}
__device__ __forceinline__ float2 two_prod(float a, float b) {
    float p = __fmul_rn(a, b);
    float e = __fmaf_rn(a, b, -p);
    return make_float2(p, e);
}
__device__ __forceinline__ float2 exp_ds(float x) {
    x = fmaxf(-30.0f, fminf(30.0f, x));
    float n  = rintf(__fmul_rn(x, 1.4426950408889634f));
    float r1 = __fmaf_rn(n, -0.693359375f, x);
    float2 p = two_prod(n, 2.1219444e-4f);
    float2 r = two_sum(r1, p.x);
    float rh = r.x;
    float rl = __fadd_rn(r.y, p.y);
    float t = 1.9841270e-4f;
    t = __fmaf_rn(t, rh, 1.3888889e-3f);
    t = __fmaf_rn(t, rh, 8.3333333e-3f);
    t = __fmaf_rn(t, rh, 4.1666667e-2f);
    t = __fmaf_rn(t, rh, 1.6666667e-1f);
    float rr   = __fmul_rn(rh, rh);
    float tail = __fmul_rn(__fmul_rn(rr, rh), t);
    tail = __fmaf_rn(rl, __fadd_rn(1.0f, rh), tail);
    float2 h2 = two_prod(rh, rh);
    float hx = __fmul_rn(0.5f, h2.x), hy = __fmul_rn(0.5f, h2.y);
    float2 a  = quick_two_sum(rh, hx);
    float al  = __fadd_rn(a.y, hy);
    float2 b  = two_sum(a.x, tail);
    float bl  = __fadd_rn(b.y, al);
    float2 c  = quick_two_sum(1.0f, b.x);
    float cl  = __fadd_rn(c.y, bl);
    float sc  = __int_as_float(((int)n + 127) << 23);
    return make_float2(__fmul_rn(c.x, sc), __fmul_rn(cl, sc));
}
__device__ __forceinline__ float2 sigmoid_ds(float x) {
    float2 E = exp_ds(-x);
    float2 D = two_sum(1.0f, E.x);
    float Dl = __fadd_rn(D.y, E.y);
    float y  = __frcp_rn(D.x);
    float e  = __fmaf_rn(-D.x, y, 1.0f);
    e        = __fmaf_rn(-Dl, y, e);
    return make_float2(y, __fmul_rn(y, e));
}
__device__ __forceinline__ float2 tanh_ds(float x) {
    float2 E = exp_ds(__fmul_rn(2.0f, x));
    float2 num = two_sum(E.x, -1.0f);
    float numl = __fadd_rn(num.y, E.y);
    float2 den = two_sum(E.x, 1.0f);
    float denl = __fadd_rn(den.y, E.y);
    float q  = __fdiv_rn(num.x, den.x);
    float rr = __fmaf_rn(-q, den.x, num.x);
    rr = __fadd_rn(rr, __fmaf_rn(-q, denl, numl));
    float ql = __fmul_rn(rr, __frcp_rn(den.x));
    return make_float2(q, ql);
}

// ---------------- 0: zero arrival slots ----------------
__global__ void zero_cnt_kernel() {
    int i = threadIdx.x;
    if (i < 128) ((int*)g_arrive)[i] = 0;
}

// ---------------- 1: input GEMM with fused gather (R14-exact) ----------------
__global__ __launch_bounds__(256) void xg_gemm_kernel(
    const int* __restrict__ x, const float* __restrict__ emb,
    const float* __restrict__ wf, const float* __restrict__ wb,
    const float* __restrict__ bihf, const float* __restrict__ bhhf,
    const float* __restrict__ bihb, const float* __restrict__ bhhb)
{
    __shared__ float ash[16][64];   // [k][m]
    __shared__ float bsh[16][64];   // [k][n]

    int dir = blockIdx.z;
    const float* W  = dir ? wb : wf;
    const float* B1 = dir ? bihb : bihf;
    const float* B2 = dir ? bhhb : bhhf;
    float* Cout = g_xg[dir];

    int t  = blockIdx.x;
    int m0 = t * 64;
    int n0 = blockIdx.y * 64;
    int tid = threadIdx.x;
    int tx = tid & 15;
    int ty = tid >> 4;

    float acc[4][4], cmp[4][4];
#pragma unroll
    for (int i = 0; i < 4; i++)
#pragma unroll
        for (int j = 0; j < 4; j++) { acc[i][j] = 0.f; cmp[i][j] = 0.f; }

    int ml = tid >> 2;        // 0..63 (row in tile == batch b)
    int kq = tid & 3;

    int tok = x[ml * TT + t];
    const float* arow = emb + (size_t)tok * EE;
    const float* brow = W + (size_t)(n0 + ml) * EE;

    for (int k0 = 0; k0 < EE; k0 += 16) {
        float4 av = *(const float4*)(arow + k0 + kq * 4);
        float4 bv = *(const float4*)(brow + k0 + kq * 4);
        ash[kq * 4 + 0][ml] = av.x; ash[kq * 4 + 1][ml] = av.y;
        ash[kq * 4 + 2][ml] = av.z; ash[kq * 4 + 3][ml] = av.w;
        bsh[kq * 4 + 0][ml] = bv.x; bsh[kq * 4 + 1][ml] = bv.y;
        bsh[kq * 4 + 2][ml] = bv.z; bsh[kq * 4 + 3][ml] = bv.w;
        __syncthreads();

        float part[4][4];
#pragma unroll
        for (int i = 0; i < 4; i++)
#pragma unroll
            for (int j = 0; j < 4; j++) part[i][j] = 0.f;

#pragma unroll
        for (int kk = 0; kk < 16; kk++) {
            float4 a4 = *(const float4*)&ash[kk][ty * 4];
            float4 b4 = *(const float4*)&bsh[kk][tx * 4];
            part[0][0] = __fmaf_rn(a4.x, b4.x, part[0][0]); part[0][1] = __fmaf_rn(a4.x, b4.y, part[0][1]);
            part[0][2] = __fmaf_rn(a4.x, b4.z, part[0][2]); part[0][3] = __fmaf_rn(a4.x, b4.w, part[0][3]);
            part[1][0] = __fmaf_rn(a4.y, b4.x, part[1][0]); part[1][1] = __fmaf_rn(a4.y, b4.y, part[1][1]);
            part[1][2] = __fmaf_rn(a4.y, b4.z, part[1][2]); part[1][3] = __fmaf_rn(a4.y, b4.w, part[1][3]);
            part[2][0] = __fmaf_rn(a4.z, b4.x, part[2][0]); part[2][1] = __fmaf_rn(a4.z, b4.y, part[2][1]);
            part[2][2] = __fmaf_rn(a4.z, b4.z, part[2][2]); part[2][3] = __fmaf_rn(a4.z, b4.w, part[2][3]);
            part[3][0] = __fmaf_rn(a4.w, b4.x, part[3][0]); part[3][1] = __fmaf_rn(a4.w, b4.y, part[3][1]);
            part[3][2] = __fmaf_rn(a4.w, b4.z, part[3][2]); part[3][3] = __fmaf_rn(a4.w, b4.w, part[3][3]);
        }
#pragma unroll
        for (int i = 0; i < 4; i++)
#pragma unroll
            for (int j = 0; j < 4; j++) KMERGE(acc[i][j], cmp[i][j], part[i][j]);
        __syncthreads();
    }

    float bias[4];
#pragma unroll
    for (int j = 0; j < 4; j++) {
        int n = n0 + tx * 4 + j;
        bias[j] = B1[n] + B2[n];
    }
#pragma unroll
    for (int i = 0; i < 4; i++) {
        float4 r;
        r.x = __fsub_rn(acc[i][0], cmp[i][0]) + bias[0];
        r.y = __fsub_rn(acc[i][1], cmp[i][1]) + bias[1];
        r.z = __fsub_rn(acc[i][2], cmp[i][2]) + bias[2];
        r.w = __fsub_rn(acc[i][3], cmp[i][3]) + bias[3];
        *(float4*)(Cout + (size_t)(m0 + ty * 4 + i) * GG + n0 + tx * 4) = r;
    }
}

// ---------------- 2: persistent BiLSTM (slot sync w/ nanosleep; gate buffer;
//                     tid0-only cumulative fence) --------------------------------
#define LSTM_SMEM_FLOATS (4096 + 16384 + 1024 + 256 + 1024)
__global__ __launch_bounds__(256) void lstm_persist_kernel(const float* __restrict__ wf,
                                                           const float* __restrict__ wb)
{
    extern __shared__ float sm[];
    float* wsh = sm;                    // [16][256]
    float* hsh = sm + 4096;             // [256][64]
    float* xsh = sm + 4096 + 16384;     // [16][64]  xg staging
    float* csh = xsh + 1024;            // [4][64]   cell state
    float* gsh = csh + 256;             // [16][64]  gate results (separate buffer)

    int tid = threadIdx.x;
    int dir = blockIdx.x >> 6;
    int g   = blockIdx.x & 63;
    const float* W = dir ? wb : wf;
    const float* xg = g_xg[dir];
    float* hbase = g_h[dir];
    volatile int* arr = (volatile int*)g_arrive[dir];

    for (int i = tid; i < 1024; i += 256) {
        int rr = i >> 6;
        int e4 = i & 63;
        int grow = (rr >> 2) * 256 + g * 4 + (rr & 3);
        *(float4*)(wsh + rr * 256 + e4 * 4) =
            *(const float4*)(W + (size_t)grow * 256 + e4 * 4);
    }
    csh[tid] = 0.f;
    __syncthreads();

    int r2 = tid >> 5;
    int b2 = tid & 31;
    int du = tid >> 6;
    int bb = tid & 63;

    for (int s = 0; s < TT; s++) {
        int t = dir ? (TT - 1 - s) : s;

        // stage this CTA's xg slice: 64 b x 4 q float4s
        {
            int b = tid >> 2, q = tid & 3;
            float4 v = *(const float4*)(xg + (size_t)(t * 64 + b) * GG + q * 256 + g * 4);
            xsh[(q * 4 + 0) * 64 + b] = v.x;
            xsh[(q * 4 + 1) * 64 + b] = v.y;
            xsh[(q * 4 + 2) * 64 + b] = v.z;
            xsh[(q * 4 + 3) * 64 + b] = v.w;
        }

        if (s > 0) {
            // distributed wait: thread i watches CTA i's slot; paced polling
            if (tid < 64) {
                while (arr[tid] < s) { __nanosleep(32); }
            }
            __syncthreads();
            int tp = dir ? (t + 1) : (t - 1);
            const float* hp = hbase + (size_t)tp * (HH * BB);
            for (int i = tid; i < 4096; i += 256)
                *(float4*)(hsh + i * 4) = *(const float4*)(hp + i * 4);
        }
        __syncthreads();

        // Kahan fp32 dot over 256 h-terms: 16 chunks of 16 (R9-exact order)
        float a00 = 0.f, a01 = 0.f, a10 = 0.f, a11 = 0.f;
        float k00 = 0.f, k01 = 0.f, k10 = 0.f, k11 = 0.f;
        if (s > 0) {
            const float* w0p = wsh + r2 * 256;
            const float* w1p = wsh + (r2 + 8) * 256;
#pragma unroll
            for (int e16 = 0; e16 < 16; e16++) {
                float p00 = 0.f, p01 = 0.f, p10 = 0.f, p11 = 0.f;
#pragma unroll
                for (int q = 0; q < 4; q++) {
                    int e4 = e16 * 4 + q;
                    float4 w0 = *(const float4*)(w0p + e4 * 4);
                    float4 w1 = *(const float4*)(w1p + e4 * 4);
                    const float* hp0 = hsh + e4 * 256 + b2;
                    float h0, h1;
                    h0 = hp0[0];   h1 = hp0[32];
                    p00 = __fmaf_rn(w0.x, h0, p00); p01 = __fmaf_rn(w0.x, h1, p01);
                    p10 = __fmaf_rn(w1.x, h0, p10); p11 = __fmaf_rn(w1.x, h1, p11);
                    h0 = hp0[64];  h1 = hp0[96];
                    p00 = __fmaf_rn(w0.y, h0, p00); p01 = __fmaf_rn(w0.y, h1, p01);
                    p10 = __fmaf_rn(w1.y, h0, p10); p11 = __fmaf_rn(w1.y, h1, p11);
                    h0 = hp0[128]; h1 = hp0[160];
                    p00 = __fmaf_rn(w0.z, h0, p00); p01 = __fmaf_rn(w0.z, h1, p01);
                    p10 = __fmaf_rn(w1.z, h0, p10); p11 = __fmaf_rn(w1.z, h1, p11);
                    h0 = hp0[192]; h1 = hp0[224];
                    p00 = __fmaf_rn(w0.w, h0, p00); p01 = __fmaf_rn(w0.w, h1, p01);
                    p10 = __fmaf_rn(w1.w, h0, p10); p11 = __fmaf_rn(w1.w, h1, p11);
                }
                KMERGE(a00, k00, p00); KMERGE(a01, k01, p01);
                KMERGE(a10, k10, p10); KMERGE(a11, k11, p11);
            }
        }
        // gates -> separate buffer (no WAR on xsh; saves one barrier)
        gsh[r2 * 64 + b2]             = xsh[r2 * 64 + b2]            + __fsub_rn(a00, k00);
        gsh[r2 * 64 + b2 + 32]        = xsh[r2 * 64 + b2 + 32]       + __fsub_rn(a01, k01);
        gsh[(r2 + 8) * 64 + b2]       = xsh[(r2 + 8) * 64 + b2]      + __fsub_rn(a10, k10);
        gsh[(r2 + 8) * 64 + b2 + 32]  = xsh[(r2 + 8) * 64 + b2 + 32] + __fsub_rn(a11, k11);
        __syncthreads();

        // activation (double-single; quantize at c and h) — R9-exact
        {
            float iv = gsh[(0 + du) * 64 + bb];
            float fv = gsh[(4 + du) * 64 + bb];
            float gv = gsh[(8 + du) * 64 + bb];
            float ov = gsh[(12 + du) * 64 + bb];
            float c  = csh[du * 64 + bb];

            float2 sf = sigmoid_ds(fv);
            float2 si = sigmoid_ds(iv);
            float2 tg = tanh_ds(gv);
            float2 p1 = two_prod(sf.x, c);
            float p1l = __fmaf_rn(sf.y, c, p1.y);
            float2 p2 = two_prod(si.x, tg.x);
            float p2l = __fmaf_rn(si.x, tg.y, __fmaf_rn(si.y, tg.x, p2.y));
            float2 sck = two_sum(p1.x, p2.x);
            float cf = __fadd_rn(sck.x, __fadd_rn(sck.y, __fadd_rn(p1l, p2l)));

            float2 so = sigmoid_ds(ov);
            float2 tc = tanh_ds(cf);
            float2 ph = two_prod(so.x, tc.x);
            float phl = __fmaf_rn(so.x, tc.y, __fmaf_rn(so.y, tc.x, ph.y));
            float hf = __fadd_rn(ph.x, phl);

            csh[du * 64 + bb] = cf;
            hbase[(size_t)t * (HH * BB) + (g * 4 + du) * 64 + bb] = hf;
        }
        __syncthreads();
        if (tid == 0) {
            __threadfence();            // cumulative: orders all threads' h STGs
            arr[g] = s + 1;             // own slot: plain store, no RMW
        }
    }
}

// ---------------- 3: emissions = kahan_dot([h_f|h_b], w_out) + b_out ----------
__global__ __launch_bounds__(256) void emis_kernel(const float* __restrict__ wout,
                                                   const float* __restrict__ bout)
{
    __shared__ float wsh[KK * 512];
    int t = blockIdx.x;
    int tid = threadIdx.x;

    for (int i = tid; i < (KK * 512) / 4; i += 256)
        *(float4*)(wsh + i * 4) = *(const float4*)(wout + i * 4);
    __syncthreads();

    int b = tid & 63;
    int kslot = tid >> 6;

    float acc[4] = {0.f, 0.f, 0.f, 0.f};
    float cmp[4] = {0.f, 0.f, 0.f, 0.f};

    const float* hf = g_h[0] + (size_t)t * (HH * BB);
    const float* hb = g_h[1] + (size_t)t * (HH * BB);

    for (int half = 0; half < 2; half++) {
        const float* hsrc = half ? hb : hf;
        int woff = half ? 256 : 0;
        for (int u0 = 0; u0 < HH; u0 += 16) {
            float part[4] = {0.f, 0.f, 0.f, 0.f};
#pragma unroll
            for (int uu = 0; uu < 16; uu++) {
                float v = hsrc[(u0 + uu) * 64 + b];
#pragma unroll
                for (int i = 0; i < 4; i++) {
                    int k = kslot + 4 * i;
                    if (k < KK)
                        part[i] = __fmaf_rn(v, wsh[k * 512 + woff + u0 + uu], part[i]);
                }
            }
#pragma unroll
            for (int i = 0; i < 4; i++) KMERGE(acc[i], cmp[i], part[i]);
        }
    }
#pragma unroll
    for (int i = 0; i < 4; i++) {
        int k = kslot + 4 * i;
        if (k < KK)
            g_emis[((size_t)t * 64 + b) * KK + k] = __fsub_rn(acc[i], cmp[i]) + bout[k];
    }
}

// ---------------- 4: CRF Viterbi, warp-per-batch, smem-resident ----------
#define VIT_EM_FLOATS (TT * 16)
#define VIT_SMEM_BYTES ((VIT_EM_FLOATS + 176 + 16) * 4 + (TT - 1) * 16)
__global__ __launch_bounds__(32) void viterbi_kernel(const float* __restrict__ start_t,
                                                     const float* __restrict__ end_t,
                                                     const float* __restrict__ trans,
                                                     float* __restrict__ out, int out_size)
{
    extern __shared__ float vsm[];
    float* em_s = vsm;                                   // [512][16]
    float* tr   = vsm + VIT_EM_FLOATS;                   // [169] (+pad)
    float* ssc  = tr + 176;                              // [16]
    unsigned char* bps = (unsigned char*)(ssc + 16);     // [511][16]

    int k = threadIdx.x;
    int b = blockIdx.x;
    bool act = (k < KK);

    for (int i = k; i < VIT_EM_FLOATS; i += 32) {
        int t = i >> 4, kk = i & 15;
        em_s[i] = (kk < KK) ? g_emis[((size_t)t * 64 + b) * KK + kk] : 0.f;
    }
    for (int i = k; i < 169; i += 32) tr[i] = trans[i];
    __syncwarp();

    float trcol[KK];
#pragma unroll
    for (int j = 0; j < KK; j++) trcol[j] = act ? tr[j * KK + k] : 0.f;

    float sc = act ? (start_t[k] + em_s[k]) : -1e30f;

    for (int t = 1; t < TT; t++) {
        if (act) ssc[k] = sc;
        __syncwarp();
        float best = -1e30f;
        int arg = 0;
        if (act) {
            float em = em_s[t * 16 + k];
            best = (ssc[0] + trcol[0]) + em;
#pragma unroll
            for (int j = 1; j < KK; j++) {
                float v = (ssc[j] + trcol[j]) + em;
                if (v > best) { best = v; arg = j; }
            }
            bps[(t - 1) * 16 + k] = (unsigned char)arg;
        }
        __syncwarp();
        sc = best;
    }

    if (act) ssc[k] = sc + end_t[k];
    __syncwarp();

    if (k == 0) {
        float best = ssc[0];
        int arg = 0;
#pragma unroll
        for (int j = 1; j < KK; j++) {
            float v = ssc[j];
            if (v > best) { best = v; arg = j; }
        }
        if (out_size >= MM + BB) out[MM + b] = best;
        int tag = arg;
        out[(size_t)b * TT + (TT - 1)] = (float)tag;
        for (int t = TT - 2; t >= 0; t--) {
            tag = bps[t * 16 + tag];
            out[(size_t)b * TT + t] = (float)tag;
        }
    }
}

// ---------------- launch ----------------
extern "C" void kernel_launch(void* const* d_in, const int* in_sizes, int n_in,
                              void* d_out, int out_size)
{
    const int*   x       = (const int*)  d_in[0];
    const float* emb     = (const float*)d_in[1];
    const float* w_ih_f  = (const float*)d_in[2];
    const float* w_hh_f  = (const float*)d_in[3];
    const float* b_ih_f  = (const float*)d_in[4];
    const float* b_hh_f  = (const float*)d_in[5];
    const float* w_ih_b  = (const float*)d_in[6];
    const float* w_hh_b  = (const float*)d_in[7];
    const float* b_ih_b  = (const float*)d_in[8];
    const float* b_hh_b  = (const float*)d_in[9];
    const float* w_out   = (const float*)d_in[10];
    const float* b_out   = (const float*)d_in[11];
    const float* start_t = (const float*)d_in[12];
    const float* end_t   = (const float*)d_in[13];
    const float* trans   = (const float*)d_in[14];
    float* out = (float*)d_out;

    cudaFuncSetAttribute(lstm_persist_kernel,
                         cudaFuncAttributeMaxDynamicSharedMemorySize,
                         LSTM_SMEM_FLOATS * 4);
    cudaFuncSetAttribute(viterbi_kernel,
                         cudaFuncAttributeMaxDynamicSharedMemorySize,
                         VIT_SMEM_BYTES);

    zero_cnt_kernel<<<1, 128>>>();
    dim3 gg(512, 16, 2);
    xg_gemm_kernel<<<gg, 256>>>(x, emb, w_ih_f, w_ih_b,
                                b_ih_f, b_hh_f, b_ih_b, b_hh_b);
    lstm_persist_kernel<<<128, 256, LSTM_SMEM_FLOATS * 4>>>(w_hh_f, w_hh_b);
    emis_kernel<<<TT, 256>>>(w_out, b_out);
    viterbi_kernel<<<64, 32, VIT_SMEM_BYTES>>>(start_t, end_t, trans, out, out_size);
}